// round 14
// baseline (speedup 1.0000x reference)
#include <cuda_runtime.h>
#include <cuda_bf16.h>
#include <cstdint>
#include <math.h>

#define SQ   400
#define BB   128
#define HH   512
#define EE   300
#define G3   1536
#define NCOL 3072

typedef unsigned long long u64;
typedef unsigned int       u32;

__device__ float g_gi[(size_t)SQ * NCOL * BB];           // [t][col(3072)][b(128)]
__device__ __nv_bfloat16 g_y0h[(size_t)SQ * BB * 1024];  // [t][b][k] hi plane
__device__ __nv_bfloat16 g_y0l[(size_t)SQ * BB * 1024];  // [t][b][k] lo plane
__device__ __nv_bfloat16 g_wh[(size_t)NCOL * 1024];      // W hi plane [col][Kpad]
__device__ __nv_bfloat16 g_wl[(size_t)NCOL * 1024];      // W lo plane
__device__ __nv_bfloat16 g_hbh[2][2][BB][HH];            // [buf][dir][b][k] h hi
__device__ __nv_bfloat16 g_hbl[2][2][BB][HH];            // [buf][dir][b][k] h lo
__device__ unsigned g_cbar[2][4];                        // per-(dir, k-chunk) producer counters

__global__ void init_kernel() {
    __nv_bfloat16* p0 = &g_hbh[0][0][0][0];
    __nv_bfloat16* p1 = &g_hbl[0][0][0][0];
    size_t n = 2ull * 2 * BB * HH;
    for (size_t i = blockIdx.x * blockDim.x + threadIdx.x; i < n; i += (size_t)gridDim.x * blockDim.x) {
        p0[i] = __float2bfloat16(0.0f);
        p1[i] = __float2bfloat16(0.0f);
    }
    if (blockIdx.x == 0 && threadIdx.x < 8) g_cbar[threadIdx.x >> 2][threadIdx.x & 3] = 0u;
}

__global__ void wsplit_kernel(const float* __restrict__ W, int K, int Kpad) {
    size_t n = (size_t)NCOL * Kpad;
    for (size_t i = blockIdx.x * blockDim.x + threadIdx.x; i < n; i += (size_t)gridDim.x * blockDim.x) {
        int col = (int)(i / Kpad), k = (int)(i % Kpad);
        float v = (k < K) ? W[(size_t)col * K + k] : 0.0f;
        __nv_bfloat16 h = __float2bfloat16(v);
        g_wh[i] = h;
        g_wl[i] = __float2bfloat16(v - __bfloat162float(h));
    }
}

// ---------------- common HMMA helpers ----------------
__device__ __forceinline__ void cpa16(u32 dst, const void* src) {
    asm volatile("cp.async.cg.shared.global [%0], [%1], 16;" :: "r"(dst), "l"(src) : "memory");
}
__device__ __forceinline__ void ldsm4(u32 &r0, u32 &r1, u32 &r2, u32 &r3, u32 addr) {
    asm volatile("ldmatrix.sync.aligned.m8n8.x4.shared.b16 {%0,%1,%2,%3}, [%4];"
                 : "=r"(r0), "=r"(r1), "=r"(r2), "=r"(r3) : "r"(addr));
}
__device__ __forceinline__ void mma16816(float* c, const u32* a, u32 b0, u32 b1) {
    asm volatile("mma.sync.aligned.m16n8k16.row.col.f32.bf16.bf16.f32 "
                 "{%0,%1,%2,%3}, {%4,%5,%6,%7}, {%8,%9}, {%0,%1,%2,%3};"
                 : "+f"(c[0]), "+f"(c[1]), "+f"(c[2]), "+f"(c[3])
                 : "r"(a[0]), "r"(a[1]), "r"(a[2]), "r"(a[3]), "r"(b0), "r"(b1));
}
__device__ __forceinline__ void spin_ge(const unsigned* p, unsigned tgt) {
    unsigned v;
    do {
        asm volatile("ld.acquire.gpu.global.u32 %0, [%1];" : "=r"(v) : "l"(p) : "memory");
    } while (v < tgt);
}

// ================= HMMA bf16-split input GEMM, occ 2 (K=32 chunks) =================
#define PITCH 80
#define TILE_B (128 * PITCH)
#define BUFB   (4 * TILE_B)
#define GEMM_SMEM (2 * BUFB)

template <bool GATHER>
__global__ __launch_bounds__(256, 2)
void gemm_tc(const float* __restrict__ emb, const int* __restrict__ X,
             const float* __restrict__ bias, int Kpad, int nch)
{
    extern __shared__ __align__(16) char sm[];
    const u32 smb = (u32)__cvta_generic_to_shared(sm);

    const int t     = blockIdx.y;
    const int nbase = blockIdx.x * 128;
    const int tid   = threadIdx.x;
    const int wid   = tid >> 5;
    const int lane  = tid & 31;
    const int row   = tid >> 1;
    const int sub   = tid & 1;
    const int wm    = wid & 3;
    const int wn    = wid >> 2;

    const float* brow_f = GATHER ? emb + (size_t)X[t * 128 + row] * EE : nullptr;

    float acc[2][8][4];
#pragma unroll
    for (int mt = 0; mt < 2; mt++)
#pragma unroll
        for (int j = 0; j < 8; j++)
#pragma unroll
            for (int e = 0; e < 4; e++) acc[mt][j][e] = 0.0f;

    u32 aoff[2], boff[4];
#pragma unroll
    for (int mt = 0; mt < 2; mt++)
        aoff[mt] = (u32)((wm * 32 + mt * 16 + (lane & 15)) * PITCH + (lane >> 4) * 16);
#pragma unroll
    for (int nt = 0; nt < 4; nt++)
        boff[nt] = (u32)((wn * 64 + nt * 16 + (lane & 7) + ((lane >> 3) & 1) * 8) * PITCH
                         + (lane >> 4) * 16);

    auto issue = [&](int c) {
        const u32 tb = smb + (u32)((c & 1) * BUFB);
        const int k0 = c * 32;
        const __nv_bfloat16* ah = g_wh + (size_t)(nbase + row) * Kpad + k0 + sub * 16;
        const __nv_bfloat16* al = g_wl + (size_t)(nbase + row) * Kpad + k0 + sub * 16;
#pragma unroll
        for (int i = 0; i < 2; i++) {
            u32 so = (u32)(row * PITCH + sub * 32 + i * 16);
            cpa16(tb + so, ah + i * 8);
            cpa16(tb + TILE_B + so, al + i * 8);
        }
        if (!GATHER) {
            const __nv_bfloat16* bh = g_y0h + ((size_t)t * 128 + row) * 1024 + k0 + sub * 16;
            const __nv_bfloat16* bl = g_y0l + ((size_t)t * 128 + row) * 1024 + k0 + sub * 16;
#pragma unroll
            for (int i = 0; i < 2; i++) {
                u32 so = (u32)(row * PITCH + sub * 32 + i * 16);
                cpa16(tb + 2 * TILE_B + so, bh + i * 8);
                cpa16(tb + 3 * TILE_B + so, bl + i * 8);
            }
        } else {
            char* buf = sm + (c & 1) * BUFB;
#pragma unroll
            for (int i = 0; i < 4; i++) {
                int k = k0 + sub * 16 + i * 4;
                float4 v = (k + 4 <= EE) ? *(const float4*)(brow_f + k) : make_float4(0, 0, 0, 0);
                u64 ph = 0, pl = 0;
#pragma unroll
                for (int jx = 0; jx < 4; jx++) {
                    float f = (&v.x)[jx];
                    __nv_bfloat16 hb = __float2bfloat16(f);
                    __nv_bfloat16 lb = __float2bfloat16(f - __bfloat162float(hb));
                    ph |= (u64)__bfloat16_as_ushort(hb) << (16 * jx);
                    pl |= (u64)__bfloat16_as_ushort(lb) << (16 * jx);
                }
                u32 so = (u32)(row * PITCH + sub * 32 + i * 8);
                *(u64*)(buf + 2 * TILE_B + so) = ph;
                *(u64*)(buf + 3 * TILE_B + so) = pl;
            }
        }
        asm volatile("cp.async.commit_group;" ::: "memory");
    };

    issue(0);
    for (int c = 0; c < nch; c++) {
        if (c + 1 < nch) {
            issue(c + 1);
            asm volatile("cp.async.wait_group 1;" ::: "memory");
        } else {
            asm volatile("cp.async.wait_group 0;" ::: "memory");
        }
        __syncthreads();

        const u32 tb = smb + (u32)((c & 1) * BUFB);
#pragma unroll
        for (int ks = 0; ks < 2; ks++) {
            const u32 kb = (u32)(ks * 32);
            u32 ah[2][4], al[2][4], bh[4][4], bl[4][4];
#pragma unroll
            for (int mt = 0; mt < 2; mt++) {
                ldsm4(ah[mt][0], ah[mt][1], ah[mt][2], ah[mt][3], tb + aoff[mt] + kb);
                ldsm4(al[mt][0], al[mt][1], al[mt][2], al[mt][3], tb + TILE_B + aoff[mt] + kb);
            }
#pragma unroll
            for (int nt = 0; nt < 4; nt++) {
                ldsm4(bh[nt][0], bh[nt][1], bh[nt][2], bh[nt][3], tb + 2 * TILE_B + boff[nt] + kb);
                ldsm4(bl[nt][0], bl[nt][1], bl[nt][2], bl[nt][3], tb + 3 * TILE_B + boff[nt] + kb);
            }
#pragma unroll
            for (int mt = 0; mt < 2; mt++)
#pragma unroll
                for (int nt = 0; nt < 4; nt++)
#pragma unroll
                    for (int hf = 0; hf < 2; hf++) {
                        float* cc = acc[mt][nt * 2 + hf];
                        mma16816(cc, ah[mt], bh[nt][hf], bh[nt][hf + 2]);
                        mma16816(cc, ah[mt], bl[nt][hf], bl[nt][hf + 2]);
                        mma16816(cc, al[mt], bh[nt][hf], bh[nt][hf + 2]);
                    }
        }
        __syncthreads();
    }

#pragma unroll
    for (int mt = 0; mt < 2; mt++) {
        const int m0 = wm * 32 + mt * 16 + (lane >> 2);
        const int m1 = m0 + 8;
        const float bv0 = bias[nbase + m0];
        const float bv1 = bias[nbase + m1];
        float* d0 = g_gi + ((size_t)t * NCOL + nbase + m0) * 128;
        float* d1 = g_gi + ((size_t)t * NCOL + nbase + m1) * 128;
#pragma unroll
        for (int j = 0; j < 8; j++) {
            const int b = wn * 64 + j * 8 + (lane & 3) * 2;
            *(float2*)(d0 + b) = make_float2(acc[mt][j][0] + bv0, acc[mt][j][1] + bv0);
            *(float2*)(d1 + b) = make_float2(acc[mt][j][2] + bv1, acc[mt][j][3] + bv1);
        }
    }
}

// ================= HMMA persistent recurrence, per-chunk dataflow sync =================
#define A_PITCH 1040
#define A_PLANE (32 * A_PITCH)
#define A_BYTES (2 * A_PLANE)                  // 66560
#define B_PITCH 272
#define B_PLANE (128 * B_PITCH)                // 34816
#define B_CHUNK (2 * B_PLANE)                  // 69632
#define RECUR_SMEM (A_BYTES + 2 * B_CHUNK)     // 205824

template <bool WRITE_Y>
__global__ __launch_bounds__(256, 1) void recur_kernel(
    const float* __restrict__ Whh, const float* __restrict__ bhh)
{
    extern __shared__ __align__(16) char sm[];
    const u32 smA = (u32)__cvta_generic_to_shared(sm);
    const u32 smB = smA + A_BYTES;
    __nv_bfloat16* y_sh = (__nv_bfloat16*)(sm + A_BYTES);        // [128][8] (reuses B buf 0)
    __nv_bfloat16* y_sl = y_sh + 128 * 8;

    const int cta   = blockIdx.x;
    const int d     = cta >> 6;
    const int jbase = (cta & 63) * 8;
    const int mychunk = (cta & 63) >> 4;       // which k-chunk my j-range feeds
    const int tid   = threadIdx.x;
    const int w     = tid >> 5;
    const int lane  = tid & 31;

    // static A (Whh slice): rows r j0-7 | z j0-7 | n j0-7 | pad, bf16 hi/lo
    for (int idx = tid; idx < 32 * 512; idx += 256) {
        int rrow = idx >> 9, k = idx & 511;
        float v = 0.0f;
        if (rrow < 24) {
            int g = rrow >> 3, jj = rrow & 7;
            v = Whh[((size_t)d * G3 + g * HH + jbase + jj) * HH + k];
        }
        __nv_bfloat16 hb = __float2bfloat16(v);
        __nv_bfloat16 lb = __float2bfloat16(v - __bfloat162float(hb));
        char* base = sm + rrow * A_PITCH + k * 2;
        *(__nv_bfloat16*)base = hb;
        *(__nv_bfloat16*)(base + A_PLANE) = lb;
    }
    const int jq = lane >> 2;
    const int jg = jbase + jq;
    const float bh_r = bhh[(size_t)d * G3 + jg];
    const float bh_z = bhh[(size_t)d * G3 + HH + jg];
    const float bh_n = bhh[(size_t)d * G3 + 2 * HH + jg];
    __syncthreads();

    u32 aoff[2][2];
#pragma unroll
    for (int pl = 0; pl < 2; pl++)
#pragma unroll
        for (int mt = 0; mt < 2; mt++)
            aoff[pl][mt] = smA + (u32)(pl * A_PLANE + (mt * 16 + (lane & 15)) * A_PITCH + (lane >> 4) * 16);
    const u32 brow_off = (u32)((16 * w + (lane & 7) + ((lane >> 3) & 1) * 8) * B_PITCH + (lane >> 4) * 16);

    const int srow  = tid & 127;
    const int shalf = tid >> 7;

    float hold[2][2];
    hold[0][0] = hold[0][1] = hold[1][0] = hold[1][1] = 0.0f;

    for (int t = 0; t < SQ; t++) {
        const int pr = t & 1, pw = pr ^ 1;
        const __nv_bfloat16* hsh = &g_hbh[pr][d][0][0];
        const __nv_bfloat16* hsl = &g_hbl[pr][d][0][0];
        const unsigned tgt = (unsigned)t * 16u;

        auto stage = [&](int c) {
            const u32 db = smB + (u32)((c & 1) * B_CHUNK);
#pragma unroll
            for (int i = 0; i < 8; i++) {
                u32 so = (u32)(srow * B_PITCH + shalf * 128 + i * 16);
                const int eo = srow * 512 + c * 128 + shalf * 64 + i * 8;
                cpa16(db + so, hsh + eo);
                cpa16(db + B_PLANE + so, hsl + eo);
            }
            asm volatile("cp.async.commit_group;" ::: "memory");
        };

        // chunk-0 producers done with step t-1?  then stage it
        spin_ge(&g_cbar[d][0], tgt);
        stage(0);

        // gi loads (independent of h)
        const float* gbase = g_gi + (size_t)t * NCOL * 128 + (size_t)(d * G3 + jg) * 128;
        float2 gi_r[2], gi_z[2], gi_n[2];
#pragma unroll
        for (int nt = 0; nt < 2; nt++) {
            const int b = 16 * w + nt * 8 + (lane & 3) * 2;
            gi_r[nt] = *(const float2*)(gbase + b);
            gi_z[nt] = *(const float2*)(gbase + (size_t)HH * 128 + b);
            gi_n[nt] = *(const float2*)(gbase + (size_t)2 * HH * 128 + b);
        }

        spin_ge(&g_cbar[d][1], tgt);
        stage(1);

        float acc[2][2][4];
#pragma unroll
        for (int mt = 0; mt < 2; mt++)
#pragma unroll
            for (int nt = 0; nt < 2; nt++)
#pragma unroll
                for (int e = 0; e < 4; e++) acc[mt][nt][e] = 0.0f;

        for (int c = 0; c < 4; c++) {
            if (c < 3) {
                asm volatile("cp.async.wait_group 1;" ::: "memory");
            } else {
                asm volatile("cp.async.wait_group 0;" ::: "memory");
            }
            __syncthreads();

            const u32 bb = smB + (u32)((c & 1) * B_CHUNK) + brow_off;
            const u32 akb = (u32)(c * 256);
#pragma unroll
            for (int ks = 0; ks < 8; ks++) {
                const u32 kb = (u32)(ks * 32);
                u32 ah[2][4], al[2][4], bhf[4], blf[4];
#pragma unroll
                for (int mt = 0; mt < 2; mt++) {
                    ldsm4(ah[mt][0], ah[mt][1], ah[mt][2], ah[mt][3], aoff[0][mt] + akb + kb);
                    ldsm4(al[mt][0], al[mt][1], al[mt][2], al[mt][3], aoff[1][mt] + akb + kb);
                }
                ldsm4(bhf[0], bhf[1], bhf[2], bhf[3], bb + kb);
                ldsm4(blf[0], blf[1], blf[2], blf[3], bb + B_PLANE + kb);
#pragma unroll
                for (int mt = 0; mt < 2; mt++)
#pragma unroll
                    for (int nt = 0; nt < 2; nt++) {
                        float* cc = acc[mt][nt];
                        mma16816(cc, ah[mt], bhf[nt], bhf[nt + 2]);
                        mma16816(cc, ah[mt], blf[nt], blf[nt + 2]);
                        mma16816(cc, al[mt], bhf[nt], bhf[nt + 2]);
                    }
            }
            __syncthreads();

            if (c < 2) {                 // buffer (c&1) is drained: refill with chunk c+2
                spin_ge(&g_cbar[d][c + 2], tgt);
                stage(c + 2);
            }
        }

        // epilogue: gate fuse, coalesced writeback via smem transpose
#pragma unroll
        for (int nt = 0; nt < 2; nt++) {
            const int b = 16 * w + nt * 8 + (lane & 3) * 2;
#pragma unroll
            for (int e = 0; e < 2; e++) {
                float gh_r = acc[0][nt][e]     + bh_r;
                float gh_z = acc[0][nt][2 + e] + bh_z;
                float gh_n = acc[1][nt][e]     + bh_n;
                float gi_rv = (e == 0) ? gi_r[nt].x : gi_r[nt].y;
                float gi_zv = (e == 0) ? gi_z[nt].x : gi_z[nt].y;
                float gi_nv = (e == 0) ? gi_n[nt].x : gi_n[nt].y;
                float r = 1.0f / (1.0f + expf(-(gi_rv + gh_r)));
                float z = 1.0f / (1.0f + expf(-(gi_zv + gh_z)));
                float n = tanhf(gi_nv + r * gh_n);
                float hnew = (1.0f - z) * n + z * hold[nt][e];
                hold[nt][e] = hnew;
                __nv_bfloat16 hb = __float2bfloat16(hnew);
                __nv_bfloat16 lb = __float2bfloat16(hnew - __bfloat162float(hb));
                y_sh[(b + e) * 8 + jq] = hb;
                y_sl[(b + e) * 8 + jq] = lb;
            }
        }
        __syncthreads();
        if (tid < 128) {
            const int b = tid;
            uint4 vh = *(uint4*)(y_sh + b * 8);
            uint4 vl = *(uint4*)(y_sl + b * 8);
            *(uint4*)&g_hbh[pw][d][b][jbase] = vh;
            *(uint4*)&g_hbl[pw][d][b][jbase] = vl;
            if (WRITE_Y) {
                size_t yo = ((size_t)t * 128 + b) * 1024 + d * HH + jbase;
                *(uint4*)(g_y0h + yo) = vh;
                *(uint4*)(g_y0l + yo) = vl;
            }
        }

        __threadfence();
        __syncthreads();        // also protects y_sh (B buf 0) before next step's stage(0)
        if (t < SQ - 1 && tid == 0) {
            asm volatile("red.relaxed.gpu.global.add.u32 [%0], 1;"
                         :: "l"(&g_cbar[d][mychunk]) : "memory");
        }
    }
}

__global__ void final_kernel(const float* __restrict__ Ws, const float* __restrict__ bs,
                             float* __restrict__ out)
{
    const int b = threadIdx.x;
    float l0 = bs[0], l1 = bs[1];
#pragma unroll 2
    for (int d = 0; d < 2; d++) {
        for (int jj = 0; jj < HH; jj++) {
            float h = __bfloat162float(g_hbh[0][d][b][jj]) + __bfloat162float(g_hbl[0][d][b][jj]);
            int c = d * HH + jj;
            l0 = fmaf(h, Ws[c], l0);
            l1 = fmaf(h, Ws[1024 + c], l1);
        }
    }
    float m = fmaxf(l0, l1);
    float lse = m + logf(expf(l0 - m) + expf(l1 - m));
    out[b * 2 + 0] = l0 - lse;
    out[b * 2 + 1] = l1 - lse;
}

extern "C" void kernel_launch(void* const* d_in, const int* in_sizes, int n_in,
                              void* d_out, int out_size)
{
    const int*   X    = (const int*)  d_in[0];
    const float* emb  = (const float*)d_in[1];
    const float* Wih0 = (const float*)d_in[2];
    const float* Whh0 = (const float*)d_in[3];
    const float* bih0 = (const float*)d_in[4];
    const float* bhh0 = (const float*)d_in[5];
    const float* Wih1 = (const float*)d_in[6];
    const float* Whh1 = (const float*)d_in[7];
    const float* bih1 = (const float*)d_in[8];
    const float* bhh1 = (const float*)d_in[9];
    const float* Ws   = (const float*)d_in[10];
    const float* bs   = (const float*)d_in[11];
    float* out = (float*)d_out;

    cudaFuncSetAttribute(recur_kernel<true>,  cudaFuncAttributeMaxDynamicSharedMemorySize, RECUR_SMEM);
    cudaFuncSetAttribute(recur_kernel<false>, cudaFuncAttributeMaxDynamicSharedMemorySize, RECUR_SMEM);
    cudaFuncSetAttribute(gemm_tc<true>,  cudaFuncAttributeMaxDynamicSharedMemorySize, GEMM_SMEM);
    cudaFuncSetAttribute(gemm_tc<false>, cudaFuncAttributeMaxDynamicSharedMemorySize, GEMM_SMEM);

    dim3 ggrid(NCOL / 128, SQ);

    // layer 0
    init_kernel<<<128, 256>>>();
    wsplit_kernel<<<480, 256>>>(Wih0, EE, 320);
    gemm_tc<true><<<ggrid, 256, GEMM_SMEM>>>(emb, X, bih0, 320, 10);
    recur_kernel<true><<<128, 256, RECUR_SMEM>>>(Whh0, bhh0);

    // layer 1
    init_kernel<<<128, 256>>>();
    wsplit_kernel<<<480, 256>>>(Wih1, 1024, 1024);
    gemm_tc<false><<<ggrid, 256, GEMM_SMEM>>>(nullptr, nullptr, bih1, 1024, 32);
    recur_kernel<false><<<128, 256, RECUR_SMEM>>>(Whh1, bhh1);

    final_kernel<<<1, 128>>>(Ws, bs, out);
}

// round 15
// speedup vs baseline: 1.0269x; 1.0269x over previous
#include <cuda_runtime.h>
#include <cuda_bf16.h>
#include <cstdint>
#include <math.h>

#define SQ   400
#define BB   128
#define HH   512
#define EE   300
#define G3   1536
#define NCOL 3072

typedef unsigned long long u64;
typedef unsigned int       u32;

__device__ float g_gi[(size_t)SQ * NCOL * BB];           // [t][col(3072)][b(128)]
__device__ __nv_bfloat16 g_y0h[(size_t)SQ * BB * 1024];  // [t][b][k] hi plane
__device__ __nv_bfloat16 g_y0l[(size_t)SQ * BB * 1024];  // [t][b][k] lo plane
__device__ __nv_bfloat16 g_wh[(size_t)NCOL * 1024];      // W hi plane [col][Kpad]
__device__ __nv_bfloat16 g_wl[(size_t)NCOL * 1024];      // W lo plane
__device__ __nv_bfloat16 g_hbh[2][2][BB][HH];            // [buf][dir][b][k] h hi
__device__ __nv_bfloat16 g_hbl[2][2][BB][HH];            // [buf][dir][b][k] h lo
__device__ unsigned g_bar2[2];                           // per-direction barrier counters

__global__ void init_kernel() {
    __nv_bfloat16* p0 = &g_hbh[0][0][0][0];
    __nv_bfloat16* p1 = &g_hbl[0][0][0][0];
    size_t n = 2ull * 2 * BB * HH;
    for (size_t i = blockIdx.x * blockDim.x + threadIdx.x; i < n; i += (size_t)gridDim.x * blockDim.x) {
        p0[i] = __float2bfloat16(0.0f);
        p1[i] = __float2bfloat16(0.0f);
    }
    if (blockIdx.x == 0 && threadIdx.x < 2) g_bar2[threadIdx.x] = 0u;
}

__global__ void wsplit_kernel(const float* __restrict__ W, int K, int Kpad) {
    size_t n = (size_t)NCOL * Kpad;
    for (size_t i = blockIdx.x * blockDim.x + threadIdx.x; i < n; i += (size_t)gridDim.x * blockDim.x) {
        int col = (int)(i / Kpad), k = (int)(i % Kpad);
        float v = (k < K) ? W[(size_t)col * K + k] : 0.0f;
        __nv_bfloat16 h = __float2bfloat16(v);
        g_wh[i] = h;
        g_wl[i] = __float2bfloat16(v - __bfloat162float(h));
    }
}

// ---------------- common HMMA helpers ----------------
__device__ __forceinline__ void cpa16(u32 dst, const void* src) {
    asm volatile("cp.async.cg.shared.global [%0], [%1], 16;" :: "r"(dst), "l"(src) : "memory");
}
__device__ __forceinline__ void ldsm4(u32 &r0, u32 &r1, u32 &r2, u32 &r3, u32 addr) {
    asm volatile("ldmatrix.sync.aligned.m8n8.x4.shared.b16 {%0,%1,%2,%3}, [%4];"
                 : "=r"(r0), "=r"(r1), "=r"(r2), "=r"(r3) : "r"(addr));
}
__device__ __forceinline__ void mma16816(float* c, const u32* a, u32 b0, u32 b1) {
    asm volatile("mma.sync.aligned.m16n8k16.row.col.f32.bf16.bf16.f32 "
                 "{%0,%1,%2,%3}, {%4,%5,%6,%7}, {%8,%9}, {%0,%1,%2,%3};"
                 : "+f"(c[0]), "+f"(c[1]), "+f"(c[2]), "+f"(c[3])
                 : "r"(a[0]), "r"(a[1]), "r"(a[2]), "r"(a[3]), "r"(b0), "r"(b1));
}

// ================= HMMA bf16-split input GEMM, occ 2 (K=32 chunks) =================
#define PITCH 80
#define TILE_B (128 * PITCH)
#define BUFB   (4 * TILE_B)
#define GEMM_SMEM (2 * BUFB)

template <bool GATHER>
__global__ __launch_bounds__(256, 2)
void gemm_tc(const float* __restrict__ emb, const int* __restrict__ X,
             const float* __restrict__ bias, int Kpad, int nch)
{
    extern __shared__ __align__(16) char sm[];
    const u32 smb = (u32)__cvta_generic_to_shared(sm);

    const int t     = blockIdx.y;
    const int nbase = blockIdx.x * 128;
    const int tid   = threadIdx.x;
    const int wid   = tid >> 5;
    const int lane  = tid & 31;
    const int row   = tid >> 1;
    const int sub   = tid & 1;
    const int wm    = wid & 3;
    const int wn    = wid >> 2;

    const float* brow_f = GATHER ? emb + (size_t)X[t * 128 + row] * EE : nullptr;

    float acc[2][8][4];
#pragma unroll
    for (int mt = 0; mt < 2; mt++)
#pragma unroll
        for (int j = 0; j < 8; j++)
#pragma unroll
            for (int e = 0; e < 4; e++) acc[mt][j][e] = 0.0f;

    u32 aoff[2], boff[4];
#pragma unroll
    for (int mt = 0; mt < 2; mt++)
        aoff[mt] = (u32)((wm * 32 + mt * 16 + (lane & 15)) * PITCH + (lane >> 4) * 16);
#pragma unroll
    for (int nt = 0; nt < 4; nt++)
        boff[nt] = (u32)((wn * 64 + nt * 16 + (lane & 7) + ((lane >> 3) & 1) * 8) * PITCH
                         + (lane >> 4) * 16);

    auto issue = [&](int c) {
        const u32 tb = smb + (u32)((c & 1) * BUFB);
        const int k0 = c * 32;
        const __nv_bfloat16* ah = g_wh + (size_t)(nbase + row) * Kpad + k0 + sub * 16;
        const __nv_bfloat16* al = g_wl + (size_t)(nbase + row) * Kpad + k0 + sub * 16;
#pragma unroll
        for (int i = 0; i < 2; i++) {
            u32 so = (u32)(row * PITCH + sub * 32 + i * 16);
            cpa16(tb + so, ah + i * 8);
            cpa16(tb + TILE_B + so, al + i * 8);
        }
        if (!GATHER) {
            const __nv_bfloat16* bh = g_y0h + ((size_t)t * 128 + row) * 1024 + k0 + sub * 16;
            const __nv_bfloat16* bl = g_y0l + ((size_t)t * 128 + row) * 1024 + k0 + sub * 16;
#pragma unroll
            for (int i = 0; i < 2; i++) {
                u32 so = (u32)(row * PITCH + sub * 32 + i * 16);
                cpa16(tb + 2 * TILE_B + so, bh + i * 8);
                cpa16(tb + 3 * TILE_B + so, bl + i * 8);
            }
        } else {
            char* buf = sm + (c & 1) * BUFB;
#pragma unroll
            for (int i = 0; i < 4; i++) {
                int k = k0 + sub * 16 + i * 4;
                float4 v = (k + 4 <= EE) ? *(const float4*)(brow_f + k) : make_float4(0, 0, 0, 0);
                u64 ph = 0, pl = 0;
#pragma unroll
                for (int jx = 0; jx < 4; jx++) {
                    float f = (&v.x)[jx];
                    __nv_bfloat16 hb = __float2bfloat16(f);
                    __nv_bfloat16 lb = __float2bfloat16(f - __bfloat162float(hb));
                    ph |= (u64)__bfloat16_as_ushort(hb) << (16 * jx);
                    pl |= (u64)__bfloat16_as_ushort(lb) << (16 * jx);
                }
                u32 so = (u32)(row * PITCH + sub * 32 + i * 8);
                *(u64*)(buf + 2 * TILE_B + so) = ph;
                *(u64*)(buf + 3 * TILE_B + so) = pl;
            }
        }
        asm volatile("cp.async.commit_group;" ::: "memory");
    };

    issue(0);
    for (int c = 0; c < nch; c++) {
        if (c + 1 < nch) {
            issue(c + 1);
            asm volatile("cp.async.wait_group 1;" ::: "memory");
        } else {
            asm volatile("cp.async.wait_group 0;" ::: "memory");
        }
        __syncthreads();

        const u32 tb = smb + (u32)((c & 1) * BUFB);
#pragma unroll
        for (int ks = 0; ks < 2; ks++) {
            const u32 kb = (u32)(ks * 32);
            u32 ah[2][4], al[2][4], bh[4][4], bl[4][4];
#pragma unroll
            for (int mt = 0; mt < 2; mt++) {
                ldsm4(ah[mt][0], ah[mt][1], ah[mt][2], ah[mt][3], tb + aoff[mt] + kb);
                ldsm4(al[mt][0], al[mt][1], al[mt][2], al[mt][3], tb + TILE_B + aoff[mt] + kb);
            }
#pragma unroll
            for (int nt = 0; nt < 4; nt++) {
                ldsm4(bh[nt][0], bh[nt][1], bh[nt][2], bh[nt][3], tb + 2 * TILE_B + boff[nt] + kb);
                ldsm4(bl[nt][0], bl[nt][1], bl[nt][2], bl[nt][3], tb + 3 * TILE_B + boff[nt] + kb);
            }
#pragma unroll
            for (int mt = 0; mt < 2; mt++)
#pragma unroll
                for (int nt = 0; nt < 4; nt++)
#pragma unroll
                    for (int hf = 0; hf < 2; hf++) {
                        float* cc = acc[mt][nt * 2 + hf];
                        mma16816(cc, ah[mt], bh[nt][hf], bh[nt][hf + 2]);
                        mma16816(cc, ah[mt], bl[nt][hf], bl[nt][hf + 2]);
                        mma16816(cc, al[mt], bh[nt][hf], bh[nt][hf + 2]);
                    }
        }
        __syncthreads();
    }

#pragma unroll
    for (int mt = 0; mt < 2; mt++) {
        const int m0 = wm * 32 + mt * 16 + (lane >> 2);
        const int m1 = m0 + 8;
        const float bv0 = bias[nbase + m0];
        const float bv1 = bias[nbase + m1];
        float* d0 = g_gi + ((size_t)t * NCOL + nbase + m0) * 128;
        float* d1 = g_gi + ((size_t)t * NCOL + nbase + m1) * 128;
#pragma unroll
        for (int j = 0; j < 8; j++) {
            const int b = wn * 64 + j * 8 + (lane & 3) * 2;
            *(float2*)(d0 + b) = make_float2(acc[mt][j][0] + bv0, acc[mt][j][1] + bv0);
            *(float2*)(d1 + b) = make_float2(acc[mt][j][2] + bv1, acc[mt][j][3] + bv1);
        }
    }
}

// ================= HMMA persistent recurrence (round-13 geometry, per-dir barrier) =================
#define A_PITCH 1040
#define A_PLANE (32 * A_PITCH)
#define A_BYTES (2 * A_PLANE)                  // 66560
#define B_PITCH 272
#define B_PLANE (128 * B_PITCH)                // 34816
#define B_CHUNK (2 * B_PLANE)                  // 69632
#define RECUR_SMEM (A_BYTES + 2 * B_CHUNK)     // 205824

template <bool WRITE_Y>
__global__ __launch_bounds__(256, 1) void recur_kernel(
    const float* __restrict__ Whh, const float* __restrict__ bhh)
{
    extern __shared__ __align__(16) char sm[];
    const u32 smA = (u32)__cvta_generic_to_shared(sm);
    const u32 smB = smA + A_BYTES;
    __nv_bfloat16* y_sh = (__nv_bfloat16*)(sm + A_BYTES);        // [128][8] (reuses B buf 0)
    __nv_bfloat16* y_sl = y_sh + 128 * 8;

    const int cta   = blockIdx.x;
    const int d     = cta >> 6;
    const int jbase = (cta & 63) * 8;
    const int tid   = threadIdx.x;
    const int w     = tid >> 5;
    const int lane  = tid & 31;

    // static A (Whh slice): rows r j0-7 | z j0-7 | n j0-7 | pad, bf16 hi/lo
    for (int idx = tid; idx < 32 * 512; idx += 256) {
        int rrow = idx >> 9, k = idx & 511;
        float v = 0.0f;
        if (rrow < 24) {
            int g = rrow >> 3, jj = rrow & 7;
            v = Whh[((size_t)d * G3 + g * HH + jbase + jj) * HH + k];
        }
        __nv_bfloat16 hb = __float2bfloat16(v);
        __nv_bfloat16 lb = __float2bfloat16(v - __bfloat162float(hb));
        char* base = sm + rrow * A_PITCH + k * 2;
        *(__nv_bfloat16*)base = hb;
        *(__nv_bfloat16*)(base + A_PLANE) = lb;
    }
    const int jq = lane >> 2;
    const int jg = jbase + jq;
    const float bh_r = bhh[(size_t)d * G3 + jg];
    const float bh_z = bhh[(size_t)d * G3 + HH + jg];
    const float bh_n = bhh[(size_t)d * G3 + 2 * HH + jg];
    __syncthreads();

    u32 aoff[2][2];
#pragma unroll
    for (int pl = 0; pl < 2; pl++)
#pragma unroll
        for (int mt = 0; mt < 2; mt++)
            aoff[pl][mt] = smA + (u32)(pl * A_PLANE + (mt * 16 + (lane & 15)) * A_PITCH + (lane >> 4) * 16);
    const u32 brow_off = (u32)((16 * w + (lane & 7) + ((lane >> 3) & 1) * 8) * B_PITCH + (lane >> 4) * 16);

    const int srow  = tid & 127;
    const int shalf = tid >> 7;

    float hold[2][2];
    hold[0][0] = hold[0][1] = hold[1][0] = hold[1][1] = 0.0f;

    for (int t = 0; t < SQ; t++) {
        const int pr = t & 1, pw = pr ^ 1;
        const __nv_bfloat16* hsh = &g_hbh[pr][d][0][0];
        const __nv_bfloat16* hsl = &g_hbl[pr][d][0][0];

        auto stage = [&](int c) {
            const u32 db = smB + (u32)((c & 1) * B_CHUNK);
#pragma unroll
            for (int i = 0; i < 8; i++) {
                u32 so = (u32)(srow * B_PITCH + shalf * 128 + i * 16);
                const int eo = srow * 512 + c * 128 + shalf * 64 + i * 8;
                cpa16(db + so, hsh + eo);
                cpa16(db + B_PLANE + so, hsl + eo);
            }
            asm volatile("cp.async.commit_group;" ::: "memory");
        };

        stage(0);

        const float* gbase = g_gi + (size_t)t * NCOL * 128 + (size_t)(d * G3 + jg) * 128;
        float2 gi_r[2], gi_z[2], gi_n[2];
#pragma unroll
        for (int nt = 0; nt < 2; nt++) {
            const int b = 16 * w + nt * 8 + (lane & 3) * 2;
            gi_r[nt] = *(const float2*)(gbase + b);
            gi_z[nt] = *(const float2*)(gbase + (size_t)HH * 128 + b);
            gi_n[nt] = *(const float2*)(gbase + (size_t)2 * HH * 128 + b);
        }

        float acc[2][2][4];
#pragma unroll
        for (int mt = 0; mt < 2; mt++)
#pragma unroll
            for (int nt = 0; nt < 2; nt++)
#pragma unroll
                for (int e = 0; e < 4; e++) acc[mt][nt][e] = 0.0f;

        for (int c = 0; c < 4; c++) {
            if (c + 1 < 4) {
                stage(c + 1);
                asm volatile("cp.async.wait_group 1;" ::: "memory");
            } else {
                asm volatile("cp.async.wait_group 0;" ::: "memory");
            }
            __syncthreads();

            const u32 bb = smB + (u32)((c & 1) * B_CHUNK) + brow_off;
            const u32 akb = (u32)(c * 256);
#pragma unroll
            for (int ks = 0; ks < 8; ks++) {
                const u32 kb = (u32)(ks * 32);
                u32 ah[2][4], al[2][4], bhf[4], blf[4];
#pragma unroll
                for (int mt = 0; mt < 2; mt++) {
                    ldsm4(ah[mt][0], ah[mt][1], ah[mt][2], ah[mt][3], aoff[0][mt] + akb + kb);
                    ldsm4(al[mt][0], al[mt][1], al[mt][2], al[mt][3], aoff[1][mt] + akb + kb);
                }
                ldsm4(bhf[0], bhf[1], bhf[2], bhf[3], bb + kb);
                ldsm4(blf[0], blf[1], blf[2], blf[3], bb + B_PLANE + kb);
#pragma unroll
                for (int mt = 0; mt < 2; mt++)
#pragma unroll
                    for (int nt = 0; nt < 2; nt++) {
                        float* cc = acc[mt][nt];
                        mma16816(cc, ah[mt], bhf[nt], bhf[nt + 2]);
                        mma16816(cc, ah[mt], blf[nt], blf[nt + 2]);
                        mma16816(cc, al[mt], bhf[nt], bhf[nt + 2]);
                    }
            }
            __syncthreads();
        }

        // epilogue: gate fuse, then coalesced writeback via smem transpose
#pragma unroll
        for (int nt = 0; nt < 2; nt++) {
            const int b = 16 * w + nt * 8 + (lane & 3) * 2;
#pragma unroll
            for (int e = 0; e < 2; e++) {
                float gh_r = acc[0][nt][e]     + bh_r;
                float gh_z = acc[0][nt][2 + e] + bh_z;
                float gh_n = acc[1][nt][e]     + bh_n;
                float gi_rv = (e == 0) ? gi_r[nt].x : gi_r[nt].y;
                float gi_zv = (e == 0) ? gi_z[nt].x : gi_z[nt].y;
                float gi_nv = (e == 0) ? gi_n[nt].x : gi_n[nt].y;
                float r = 1.0f / (1.0f + expf(-(gi_rv + gh_r)));
                float z = 1.0f / (1.0f + expf(-(gi_zv + gh_z)));
                float n = tanhf(gi_nv + r * gh_n);
                float hnew = (1.0f - z) * n + z * hold[nt][e];
                hold[nt][e] = hnew;
                __nv_bfloat16 hb = __float2bfloat16(hnew);
                __nv_bfloat16 lb = __float2bfloat16(hnew - __bfloat162float(hb));
                y_sh[(b + e) * 8 + jq] = hb;
                y_sl[(b + e) * 8 + jq] = lb;
            }
        }
        __syncthreads();
        if (tid < 128) {
            const int b = tid;
            uint4 vh = *(uint4*)(y_sh + b * 8);
            uint4 vl = *(uint4*)(y_sl + b * 8);
            *(uint4*)&g_hbh[pw][d][b][jbase] = vh;
            *(uint4*)&g_hbl[pw][d][b][jbase] = vl;
            if (WRITE_Y) {
                size_t yo = ((size_t)t * 128 + b) * 1024 + d * HH + jbase;
                *(uint4*)(g_y0h + yo) = vh;
                *(uint4*)(g_y0l + yo) = vl;
            }
        }

        if (t < SQ - 1) {
            __threadfence();
            __syncthreads();
            if (tid == 0) {
                atomicAdd(&g_bar2[d], 1u);
                const unsigned target = (unsigned)(t + 1) * 64u;
                while (*(volatile unsigned*)&g_bar2[d] < target) { }
            }
            __syncthreads();
            __threadfence();
        }
    }
}

__global__ void final_kernel(const float* __restrict__ Ws, const float* __restrict__ bs,
                             float* __restrict__ out)
{
    const int b = threadIdx.x;
    float l0 = bs[0], l1 = bs[1];
#pragma unroll 2
    for (int d = 0; d < 2; d++) {
        for (int jj = 0; jj < HH; jj++) {
            float h = __bfloat162float(g_hbh[0][d][b][jj]) + __bfloat162float(g_hbl[0][d][b][jj]);
            int c = d * HH + jj;
            l0 = fmaf(h, Ws[c], l0);
            l1 = fmaf(h, Ws[1024 + c], l1);
        }
    }
    float m = fmaxf(l0, l1);
    float lse = m + logf(expf(l0 - m) + expf(l1 - m));
    out[b * 2 + 0] = l0 - lse;
    out[b * 2 + 1] = l1 - lse;
}

extern "C" void kernel_launch(void* const* d_in, const int* in_sizes, int n_in,
                              void* d_out, int out_size)
{
    const int*   X    = (const int*)  d_in[0];
    const float* emb  = (const float*)d_in[1];
    const float* Wih0 = (const float*)d_in[2];
    const float* Whh0 = (const float*)d_in[3];
    const float* bih0 = (const float*)d_in[4];
    const float* bhh0 = (const float*)d_in[5];
    const float* Wih1 = (const float*)d_in[6];
    const float* Whh1 = (const float*)d_in[7];
    const float* bih1 = (const float*)d_in[8];
    const float* bhh1 = (const float*)d_in[9];
    const float* Ws   = (const float*)d_in[10];
    const float* bs   = (const float*)d_in[11];
    float* out = (float*)d_out;

    cudaFuncSetAttribute(recur_kernel<true>,  cudaFuncAttributeMaxDynamicSharedMemorySize, RECUR_SMEM);
    cudaFuncSetAttribute(recur_kernel<false>, cudaFuncAttributeMaxDynamicSharedMemorySize, RECUR_SMEM);
    cudaFuncSetAttribute(gemm_tc<true>,  cudaFuncAttributeMaxDynamicSharedMemorySize, GEMM_SMEM);
    cudaFuncSetAttribute(gemm_tc<false>, cudaFuncAttributeMaxDynamicSharedMemorySize, GEMM_SMEM);

    dim3 ggrid(NCOL / 128, SQ);

    // layer 0
    init_kernel<<<128, 256>>>();
    wsplit_kernel<<<480, 256>>>(Wih0, EE, 320);
    gemm_tc<true><<<ggrid, 256, GEMM_SMEM>>>(emb, X, bih0, 320, 10);
    recur_kernel<true><<<128, 256, RECUR_SMEM>>>(Whh0, bhh0);

    // layer 1
    init_kernel<<<128, 256>>>();
    wsplit_kernel<<<480, 256>>>(Wih1, 1024, 1024);
    gemm_tc<false><<<ggrid, 256, GEMM_SMEM>>>(nullptr, nullptr, bih1, 1024, 32);
    recur_kernel<false><<<128, 256, RECUR_SMEM>>>(Whh1, bhh1);

    final_kernel<<<1, 128>>>(Ws, bs, out);
}

// round 16
// speedup vs baseline: 1.0475x; 1.0200x over previous
#include <cuda_runtime.h>
#include <cuda_bf16.h>
#include <cstdint>
#include <math.h>

#define SQ   400
#define BB   128
#define HH   512
#define EE   300
#define G3   1536
#define NCOL 3072

typedef unsigned long long u64;
typedef unsigned int       u32;

__device__ float g_gi[(size_t)SQ * NCOL * BB];           // [t][col(3072)][b(128)]
__device__ __nv_bfloat16 g_y0h[(size_t)SQ * BB * 1024];  // [t][b][k] hi plane
__device__ __nv_bfloat16 g_y0l[(size_t)SQ * BB * 1024];  // [t][b][k] lo plane
__device__ __nv_bfloat16 g_wh[(size_t)NCOL * 1024];      // W hi plane [col][Kpad]
__device__ __nv_bfloat16 g_wl[(size_t)NCOL * 1024];      // W lo plane
__device__ __nv_bfloat16 g_hbh[2][2][BB][HH];            // [buf][dir][b][k] h hi
__device__ __nv_bfloat16 g_hbl[2][2][BB][HH];            // [buf][dir][b][k] h lo
__device__ unsigned g_bar2[2];                           // per-direction barrier counters

__global__ void init_kernel() {
    __nv_bfloat16* p0 = &g_hbh[0][0][0][0];
    __nv_bfloat16* p1 = &g_hbl[0][0][0][0];
    size_t n = 2ull * 2 * BB * HH;
    for (size_t i = blockIdx.x * blockDim.x + threadIdx.x; i < n; i += (size_t)gridDim.x * blockDim.x) {
        p0[i] = __float2bfloat16(0.0f);
        p1[i] = __float2bfloat16(0.0f);
    }
    if (blockIdx.x == 0 && threadIdx.x < 2) g_bar2[threadIdx.x] = 0u;
}

__global__ void wsplit_kernel(const float* __restrict__ W, int K, int Kpad) {
    size_t n = (size_t)NCOL * Kpad;
    for (size_t i = blockIdx.x * blockDim.x + threadIdx.x; i < n; i += (size_t)gridDim.x * blockDim.x) {
        int col = (int)(i / Kpad), k = (int)(i % Kpad);
        float v = (k < K) ? W[(size_t)col * K + k] : 0.0f;
        __nv_bfloat16 h = __float2bfloat16(v);
        g_wh[i] = h;
        g_wl[i] = __float2bfloat16(v - __bfloat162float(h));
    }
}

// ---------------- common HMMA helpers ----------------
__device__ __forceinline__ void cpa16(u32 dst, const void* src) {
    asm volatile("cp.async.cg.shared.global [%0], [%1], 16;" :: "r"(dst), "l"(src) : "memory");
}
__device__ __forceinline__ void ldsm4(u32 &r0, u32 &r1, u32 &r2, u32 &r3, u32 addr) {
    asm volatile("ldmatrix.sync.aligned.m8n8.x4.shared.b16 {%0,%1,%2,%3}, [%4];"
                 : "=r"(r0), "=r"(r1), "=r"(r2), "=r"(r3) : "r"(addr));
}
__device__ __forceinline__ void mma16816(float* c, const u32* a, u32 b0, u32 b1) {
    asm volatile("mma.sync.aligned.m16n8k16.row.col.f32.bf16.bf16.f32 "
                 "{%0,%1,%2,%3}, {%4,%5,%6,%7}, {%8,%9}, {%0,%1,%2,%3};"
                 : "+f"(c[0]), "+f"(c[1]), "+f"(c[2]), "+f"(c[3])
                 : "r"(a[0]), "r"(a[1]), "r"(a[2]), "r"(a[3]), "r"(b0), "r"(b1));
}

// ================= HMMA bf16-split input GEMM, occ 2 (K=32 chunks) =================
#define PITCH 80
#define TILE_B (128 * PITCH)
#define BUFB   (4 * TILE_B)
#define GEMM_SMEM (2 * BUFB)

template <bool GATHER>
__global__ __launch_bounds__(256, 2)
void gemm_tc(const float* __restrict__ emb, const int* __restrict__ X,
             const float* __restrict__ bias, int Kpad, int nch)
{
    extern __shared__ __align__(16) char sm[];
    const u32 smb = (u32)__cvta_generic_to_shared(sm);

    const int t     = blockIdx.y;
    const int nbase = blockIdx.x * 128;
    const int tid   = threadIdx.x;
    const int wid   = tid >> 5;
    const int lane  = tid & 31;
    const int row   = tid >> 1;
    const int sub   = tid & 1;
    const int wm    = wid & 3;
    const int wn    = wid >> 2;

    const float* brow_f = GATHER ? emb + (size_t)X[t * 128 + row] * EE : nullptr;

    float acc[2][8][4];
#pragma unroll
    for (int mt = 0; mt < 2; mt++)
#pragma unroll
        for (int j = 0; j < 8; j++)
#pragma unroll
            for (int e = 0; e < 4; e++) acc[mt][j][e] = 0.0f;

    u32 aoff[2], boff[4];
#pragma unroll
    for (int mt = 0; mt < 2; mt++)
        aoff[mt] = (u32)((wm * 32 + mt * 16 + (lane & 15)) * PITCH + (lane >> 4) * 16);
#pragma unroll
    for (int nt = 0; nt < 4; nt++)
        boff[nt] = (u32)((wn * 64 + nt * 16 + (lane & 7) + ((lane >> 3) & 1) * 8) * PITCH
                         + (lane >> 4) * 16);

    auto issue = [&](int c) {
        const u32 tb = smb + (u32)((c & 1) * BUFB);
        const int k0 = c * 32;
        const __nv_bfloat16* ah = g_wh + (size_t)(nbase + row) * Kpad + k0 + sub * 16;
        const __nv_bfloat16* al = g_wl + (size_t)(nbase + row) * Kpad + k0 + sub * 16;
#pragma unroll
        for (int i = 0; i < 2; i++) {
            u32 so = (u32)(row * PITCH + sub * 32 + i * 16);
            cpa16(tb + so, ah + i * 8);
            cpa16(tb + TILE_B + so, al + i * 8);
        }
        if (!GATHER) {
            const __nv_bfloat16* bh = g_y0h + ((size_t)t * 128 + row) * 1024 + k0 + sub * 16;
            const __nv_bfloat16* bl = g_y0l + ((size_t)t * 128 + row) * 1024 + k0 + sub * 16;
#pragma unroll
            for (int i = 0; i < 2; i++) {
                u32 so = (u32)(row * PITCH + sub * 32 + i * 16);
                cpa16(tb + 2 * TILE_B + so, bh + i * 8);
                cpa16(tb + 3 * TILE_B + so, bl + i * 8);
            }
        } else {
            char* buf = sm + (c & 1) * BUFB;
#pragma unroll
            for (int i = 0; i < 4; i++) {
                int k = k0 + sub * 16 + i * 4;
                float4 v = (k + 4 <= EE) ? *(const float4*)(brow_f + k) : make_float4(0, 0, 0, 0);
                u64 ph = 0, pl = 0;
#pragma unroll
                for (int jx = 0; jx < 4; jx++) {
                    float f = (&v.x)[jx];
                    __nv_bfloat16 hb = __float2bfloat16(f);
                    __nv_bfloat16 lb = __float2bfloat16(f - __bfloat162float(hb));
                    ph |= (u64)__bfloat16_as_ushort(hb) << (16 * jx);
                    pl |= (u64)__bfloat16_as_ushort(lb) << (16 * jx);
                }
                u32 so = (u32)(row * PITCH + sub * 32 + i * 8);
                *(u64*)(buf + 2 * TILE_B + so) = ph;
                *(u64*)(buf + 3 * TILE_B + so) = pl;
            }
        }
        asm volatile("cp.async.commit_group;" ::: "memory");
    };

    issue(0);
    for (int c = 0; c < nch; c++) {
        if (c + 1 < nch) {
            issue(c + 1);
            asm volatile("cp.async.wait_group 1;" ::: "memory");
        } else {
            asm volatile("cp.async.wait_group 0;" ::: "memory");
        }
        __syncthreads();

        const u32 tb = smb + (u32)((c & 1) * BUFB);
#pragma unroll
        for (int ks = 0; ks < 2; ks++) {
            const u32 kb = (u32)(ks * 32);
            u32 ah[2][4], al[2][4], bh[4][4], bl[4][4];
#pragma unroll
            for (int mt = 0; mt < 2; mt++) {
                ldsm4(ah[mt][0], ah[mt][1], ah[mt][2], ah[mt][3], tb + aoff[mt] + kb);
                ldsm4(al[mt][0], al[mt][1], al[mt][2], al[mt][3], tb + TILE_B + aoff[mt] + kb);
            }
#pragma unroll
            for (int nt = 0; nt < 4; nt++) {
                ldsm4(bh[nt][0], bh[nt][1], bh[nt][2], bh[nt][3], tb + 2 * TILE_B + boff[nt] + kb);
                ldsm4(bl[nt][0], bl[nt][1], bl[nt][2], bl[nt][3], tb + 3 * TILE_B + boff[nt] + kb);
            }
#pragma unroll
            for (int mt = 0; mt < 2; mt++)
#pragma unroll
                for (int nt = 0; nt < 4; nt++)
#pragma unroll
                    for (int hf = 0; hf < 2; hf++) {
                        float* cc = acc[mt][nt * 2 + hf];
                        mma16816(cc, ah[mt], bh[nt][hf], bh[nt][hf + 2]);
                        mma16816(cc, ah[mt], bl[nt][hf], bl[nt][hf + 2]);
                        mma16816(cc, al[mt], bh[nt][hf], bh[nt][hf + 2]);
                    }
        }
        __syncthreads();
    }

#pragma unroll
    for (int mt = 0; mt < 2; mt++) {
        const int m0 = wm * 32 + mt * 16 + (lane >> 2);
        const int m1 = m0 + 8;
        const float bv0 = bias[nbase + m0];
        const float bv1 = bias[nbase + m1];
        float* d0 = g_gi + ((size_t)t * NCOL + nbase + m0) * 128;
        float* d1 = g_gi + ((size_t)t * NCOL + nbase + m1) * 128;
#pragma unroll
        for (int j = 0; j < 8; j++) {
            const int b = wn * 64 + j * 8 + (lane & 3) * 2;
            *(float2*)(d0 + b) = make_float2(acc[mt][j][0] + bv0, acc[mt][j][1] + bv0);
            *(float2*)(d1 + b) = make_float2(acc[mt][j][2] + bv1, acc[mt][j][3] + bv1);
        }
    }
}

// ================= HMMA persistent recurrence: chunk skew + trimmed tail =================
#define A_PITCH 1040
#define A_PLANE (32 * A_PITCH)
#define A_BYTES (2 * A_PLANE)                  // 66560
#define B_PITCH 272
#define B_PLANE (128 * B_PITCH)                // 34816
#define B_CHUNK (2 * B_PLANE)                  // 69632
#define RECUR_SMEM (A_BYTES + 2 * B_CHUNK)     // 205824

template <bool WRITE_Y>
__global__ __launch_bounds__(256, 1) void recur_kernel(
    const float* __restrict__ Whh, const float* __restrict__ bhh)
{
    extern __shared__ __align__(16) char sm[];
    const u32 smA = (u32)__cvta_generic_to_shared(sm);
    const u32 smB = smA + A_BYTES;
    __nv_bfloat16* y_sh = (__nv_bfloat16*)(sm + A_BYTES);        // [128][8] (reuses B buf 0)
    __nv_bfloat16* y_sl = y_sh + 128 * 8;

    const int cta   = blockIdx.x;
    const int d     = cta >> 6;
    const int jbase = (cta & 63) * 8;
    const int skew  = cta & 3;                 // chunk-order rotation
    const int tid   = threadIdx.x;
    const int w     = tid >> 5;
    const int lane  = tid & 31;

    // static A (Whh slice): rows r j0-7 | z j0-7 | n j0-7 | pad, bf16 hi/lo
    for (int idx = tid; idx < 32 * 512; idx += 256) {
        int rrow = idx >> 9, k = idx & 511;
        float v = 0.0f;
        if (rrow < 24) {
            int g = rrow >> 3, jj = rrow & 7;
            v = Whh[((size_t)d * G3 + g * HH + jbase + jj) * HH + k];
        }
        __nv_bfloat16 hb = __float2bfloat16(v);
        __nv_bfloat16 lb = __float2bfloat16(v - __bfloat162float(hb));
        char* base = sm + rrow * A_PITCH + k * 2;
        *(__nv_bfloat16*)base = hb;
        *(__nv_bfloat16*)(base + A_PLANE) = lb;
    }
    const int jq = lane >> 2;
    const int jg = jbase + jq;
    const float bh_r = bhh[(size_t)d * G3 + jg];
    const float bh_z = bhh[(size_t)d * G3 + HH + jg];
    const float bh_n = bhh[(size_t)d * G3 + 2 * HH + jg];
    __syncthreads();

    u32 aoff[2][2];
#pragma unroll
    for (int pl = 0; pl < 2; pl++)
#pragma unroll
        for (int mt = 0; mt < 2; mt++)
            aoff[pl][mt] = smA + (u32)(pl * A_PLANE + (mt * 16 + (lane & 15)) * A_PITCH + (lane >> 4) * 16);
    const u32 brow_off = (u32)((16 * w + (lane & 7) + ((lane >> 3) & 1) * 8) * B_PITCH + (lane >> 4) * 16);

    const int srow  = tid & 127;
    const int shalf = tid >> 7;

    float hold[2][2];
    hold[0][0] = hold[0][1] = hold[1][0] = hold[1][1] = 0.0f;

    for (int t = 0; t < SQ; t++) {
        const int pr = t & 1, pw = pr ^ 1;
        const __nv_bfloat16* hsh = &g_hbh[pr][d][0][0];
        const __nv_bfloat16* hsl = &g_hbl[pr][d][0][0];

        // stage logical position p -> physical chunk (p+skew)&3 into buffer p&1
        auto stage = [&](int p) {
            const int ch = (p + skew) & 3;
            const u32 db = smB + (u32)((p & 1) * B_CHUNK);
#pragma unroll
            for (int i = 0; i < 8; i++) {
                u32 so = (u32)(srow * B_PITCH + shalf * 128 + i * 16);
                const int eo = srow * 512 + ch * 128 + shalf * 64 + i * 8;
                cpa16(db + so, hsh + eo);
                cpa16(db + B_PLANE + so, hsl + eo);
            }
            asm volatile("cp.async.commit_group;" ::: "memory");
        };

        stage(0);

        const float* gbase = g_gi + (size_t)t * NCOL * 128 + (size_t)(d * G3 + jg) * 128;
        float2 gi_r[2], gi_z[2], gi_n[2];
#pragma unroll
        for (int nt = 0; nt < 2; nt++) {
            const int b = 16 * w + nt * 8 + (lane & 3) * 2;
            gi_r[nt] = *(const float2*)(gbase + b);
            gi_z[nt] = *(const float2*)(gbase + (size_t)HH * 128 + b);
            gi_n[nt] = *(const float2*)(gbase + (size_t)2 * HH * 128 + b);
        }

        float acc[2][2][4];
#pragma unroll
        for (int mt = 0; mt < 2; mt++)
#pragma unroll
            for (int nt = 0; nt < 2; nt++)
#pragma unroll
                for (int e = 0; e < 4; e++) acc[mt][nt][e] = 0.0f;

        for (int p = 0; p < 4; p++) {
            if (p + 1 < 4) {
                stage(p + 1);
                asm volatile("cp.async.wait_group 1;" ::: "memory");
            } else {
                asm volatile("cp.async.wait_group 0;" ::: "memory");
            }
            __syncthreads();

            const u32 bb = smB + (u32)((p & 1) * B_CHUNK) + brow_off;
            const u32 akb = (u32)(((p + skew) & 3) * 256);
#pragma unroll
            for (int ks = 0; ks < 8; ks++) {
                const u32 kb = (u32)(ks * 32);
                u32 ah[2][4], al[2][4], bhf[4], blf[4];
#pragma unroll
                for (int mt = 0; mt < 2; mt++) {
                    ldsm4(ah[mt][0], ah[mt][1], ah[mt][2], ah[mt][3], aoff[0][mt] + akb + kb);
                    ldsm4(al[mt][0], al[mt][1], al[mt][2], al[mt][3], aoff[1][mt] + akb + kb);
                }
                ldsm4(bhf[0], bhf[1], bhf[2], bhf[3], bb + kb);
                ldsm4(blf[0], blf[1], blf[2], blf[3], bb + B_PLANE + kb);
#pragma unroll
                for (int mt = 0; mt < 2; mt++)
#pragma unroll
                    for (int nt = 0; nt < 2; nt++) {
                        float* cc = acc[mt][nt];
                        mma16816(cc, ah[mt], bhf[nt], bhf[nt + 2]);
                        mma16816(cc, ah[mt], blf[nt], blf[nt + 2]);
                        mma16816(cc, al[mt], bhf[nt], bhf[nt + 2]);
                    }
            }
            __syncthreads();
        }

        // gate fuse into smem transpose tile
#pragma unroll
        for (int nt = 0; nt < 2; nt++) {
            const int b = 16 * w + nt * 8 + (lane & 3) * 2;
#pragma unroll
            for (int e = 0; e < 2; e++) {
                float gh_r = acc[0][nt][e]     + bh_r;
                float gh_z = acc[0][nt][2 + e] + bh_z;
                float gh_n = acc[1][nt][e]     + bh_n;
                float gi_rv = (e == 0) ? gi_r[nt].x : gi_r[nt].y;
                float gi_zv = (e == 0) ? gi_z[nt].x : gi_z[nt].y;
                float gi_nv = (e == 0) ? gi_n[nt].x : gi_n[nt].y;
                float r = 1.0f / (1.0f + expf(-(gi_rv + gh_r)));
                float z = 1.0f / (1.0f + expf(-(gi_zv + gh_z)));
                float n = tanhf(gi_nv + r * gh_n);
                float hnew = (1.0f - z) * n + z * hold[nt][e];
                hold[nt][e] = hnew;
                __nv_bfloat16 hb = __float2bfloat16(hnew);
                __nv_bfloat16 lb = __float2bfloat16(hnew - __bfloat162float(hb));
                y_sh[(b + e) * 8 + jq] = hb;
                y_sl[(b + e) * 8 + jq] = lb;
            }
        }
        __syncthreads();

        // coalesced h writeback (peers wait on this), then arrive; y0 after arrive
        uint4 vh, vl;
        const bool wr = (tid < 128);
        if (wr) {
            vh = *(uint4*)(y_sh + tid * 8);
            vl = *(uint4*)(y_sl + tid * 8);
            *(uint4*)&g_hbh[pw][d][tid][jbase] = vh;
            *(uint4*)&g_hbl[pw][d][tid][jbase] = vl;
        }

        if (t < SQ - 1) {
            __threadfence();
            __syncthreads();
            if (tid == 0) atomicAdd(&g_bar2[d], 1u);
        }

        if (WRITE_Y && wr) {
            size_t yo = ((size_t)t * 128 + tid) * 1024 + d * HH + jbase;
            *(uint4*)(g_y0h + yo) = vh;
            *(uint4*)(g_y0l + yo) = vl;
        }

        if (t < SQ - 1) {
            if (tid == 0) {
                const unsigned target = (unsigned)(t + 1) * 64u;
                unsigned v;
                do {
                    asm volatile("ld.acquire.gpu.global.u32 %0, [%1];"
                                 : "=r"(v) : "l"(&g_bar2[d]) : "memory");
                } while (v < target);
            }
            __syncthreads();
        }
    }
}

__global__ void final_kernel(const float* __restrict__ Ws, const float* __restrict__ bs,
                             float* __restrict__ out)
{
    const int b = threadIdx.x;
    float l0 = bs[0], l1 = bs[1];
#pragma unroll 2
    for (int d = 0; d < 2; d++) {
        for (int jj = 0; jj < HH; jj++) {
            float h = __bfloat162float(g_hbh[0][d][b][jj]) + __bfloat162float(g_hbl[0][d][b][jj]);
            int c = d * HH + jj;
            l0 = fmaf(h, Ws[c], l0);
            l1 = fmaf(h, Ws[1024 + c], l1);
        }
    }
    float m = fmaxf(l0, l1);
    float lse = m + logf(expf(l0 - m) + expf(l1 - m));
    out[b * 2 + 0] = l0 - lse;
    out[b * 2 + 1] = l1 - lse;
}

extern "C" void kernel_launch(void* const* d_in, const int* in_sizes, int n_in,
                              void* d_out, int out_size)
{
    const int*   X    = (const int*)  d_in[0];
    const float* emb  = (const float*)d_in[1];
    const float* Wih0 = (const float*)d_in[2];
    const float* Whh0 = (const float*)d_in[3];
    const float* bih0 = (const float*)d_in[4];
    const float* bhh0 = (const float*)d_in[5];
    const float* Wih1 = (const float*)d_in[6];
    const float* Whh1 = (const float*)d_in[7];
    const float* bih1 = (const float*)d_in[8];
    const float* bhh1 = (const float*)d_in[9];
    const float* Ws   = (const float*)d_in[10];
    const float* bs   = (const float*)d_in[11];
    float* out = (float*)d_out;

    cudaFuncSetAttribute(recur_kernel<true>,  cudaFuncAttributeMaxDynamicSharedMemorySize, RECUR_SMEM);
    cudaFuncSetAttribute(recur_kernel<false>, cudaFuncAttributeMaxDynamicSharedMemorySize, RECUR_SMEM);
    cudaFuncSetAttribute(gemm_tc<true>,  cudaFuncAttributeMaxDynamicSharedMemorySize, GEMM_SMEM);
    cudaFuncSetAttribute(gemm_tc<false>, cudaFuncAttributeMaxDynamicSharedMemorySize, GEMM_SMEM);

    dim3 ggrid(NCOL / 128, SQ);

    // layer 0
    init_kernel<<<128, 256>>>();
    wsplit_kernel<<<480, 256>>>(Wih0, EE, 320);
    gemm_tc<true><<<ggrid, 256, GEMM_SMEM>>>(emb, X, bih0, 320, 10);
    recur_kernel<true><<<128, 256, RECUR_SMEM>>>(Whh0, bhh0);

    // layer 1
    init_kernel<<<128, 256>>>();
    wsplit_kernel<<<480, 256>>>(Wih1, 1024, 1024);
    gemm_tc<false><<<ggrid, 256, GEMM_SMEM>>>(nullptr, nullptr, bih1, 1024, 32);
    recur_kernel<false><<<128, 256, RECUR_SMEM>>>(Whh1, bhh1);

    final_kernel<<<1, 128>>>(Ws, bs, out);
}